// round 9
// baseline (speedup 1.0000x reference)
#include <cuda_runtime.h>

// B=8192, D=512, NUM_CLASSES=90, K=8
// loss = mean_b [ sum_k w_k d_k ],  d_bk = 1 + <x_b, centers[label_b, k]>, w = d/sum_k d
//
// Numerics hypothesis: reference = eager JAX on aarch64 CPU (Grace), dot
// vectorized NEON VF=4 with 2-way unroll/peel (Eigen redux / LLVM IC=2):
//   two 4-wide packet accumulators:
//     accA.lane[j] += a[8i + j]     * x[8i + j]       (vfmaq, fused)
//     accB.lane[j] += a[8i + 4 + j] * x[8i + 4 + j]
//   combine: v = accA + accB (vector add), then pairwise horizontal
//   (v0+v1)+(v2+v3)  [vaddvq_f32 / faddp order].
// Epilogue f32, one rounding per op, k-ascending; batch mean in double.

__device__ double g_partials[256];

__global__ __launch_bounds__(256) void loss_main(
    const float* __restrict__ x,
    const float* __restrict__ centers,
    const int* __restrict__ labels)
{
    const int t = blockIdx.x * 256 + threadIdx.x;   // 65536 threads
    const int b = t >> 3;                           // sample 0..8191
    const int k = t & 7;                            // center 0..7

    const int lbl = labels[b];                      // broadcast across the 8 k-lanes

    const float4* __restrict__ xp =
        reinterpret_cast<const float4*>(x + (size_t)b * 512);
    const float4* __restrict__ cp =
        reinterpret_cast<const float4*>(centers + ((size_t)lbl * 8 + k) * 512);

    // two 4-wide packet accumulators, 64 serial steps of 8 elements
    float4 va = make_float4(0.f, 0.f, 0.f, 0.f);
    float4 vb = make_float4(0.f, 0.f, 0.f, 0.f);
#pragma unroll 8
    for (int i = 0; i < 64; ++i) {
        float4 x0 = xp[2 * i];
        float4 x1 = xp[2 * i + 1];
        float4 c0 = cp[2 * i];
        float4 c1 = cp[2 * i + 1];
        va.x = fmaf(x0.x, c0.x, va.x);
        va.y = fmaf(x0.y, c0.y, va.y);
        va.z = fmaf(x0.z, c0.z, va.z);
        va.w = fmaf(x0.w, c0.w, va.w);
        vb.x = fmaf(x1.x, c1.x, vb.x);
        vb.y = fmaf(x1.y, c1.y, vb.y);
        vb.z = fmaf(x1.z, c1.z, vb.z);
        vb.w = fmaf(x1.w, c1.w, vb.w);
    }
    // combine packets: vector add, then NEON pairwise horizontal sum
    const float v0 = __fadd_rn(va.x, vb.x);
    const float v1 = __fadd_rn(va.y, vb.y);
    const float v2 = __fadd_rn(va.z, vb.z);
    const float v3 = __fadd_rn(va.w, vb.w);
    const float dot = __fadd_rn(__fadd_rn(v0, v1), __fadd_rn(v2, v3));
    const float d = __fadd_rn(1.0f, dot);

    // gather the 8 d_k of this sample to its leader lane
    float dk[8];
    const int lane = threadIdx.x & 31;
    const int base = lane & ~7;
#pragma unroll
    for (int j = 0; j < 8; ++j)
        dk[j] = __shfl_sync(0xFFFFFFFFu, d, base + j);

    __shared__ double sh[32];
    if (k == 0) {
        // s1: serial sum, k ascending
        float s1 = dk[0];
#pragma unroll
        for (int j = 1; j < 8; ++j) s1 = __fadd_rn(s1, dk[j]);

        // sum_k (d_k/s1)*d_k : div, mul, add each rounded separately
        float accw = 0.f;
#pragma unroll
        for (int j = 0; j < 8; ++j) {
            float w = __fdiv_rn(dk[j], s1);
            float p = __fmul_rn(w, dk[j]);
            accw = __fadd_rn(accw, p);
        }
        sh[threadIdx.x >> 3] = (double)accw;
    }
    __syncthreads();
    if (threadIdx.x == 0) {
        double s = 0.0;
#pragma unroll
        for (int j = 0; j < 32; ++j) s += sh[j];
        g_partials[blockIdx.x] = s;
    }
}

__global__ __launch_bounds__(256) void loss_reduce(float* __restrict__ out)
{
    __shared__ double sh[8];
    const int tid = threadIdx.x;
    const int lane = tid & 31;
    const int w = tid >> 5;

    double v = g_partials[tid];   // 256 partials
#pragma unroll
    for (int m = 16; m >= 1; m >>= 1)
        v += __shfl_xor_sync(0xFFFFFFFFu, v, m);
    if (lane == 0) sh[w] = v;
    __syncthreads();
    if (tid == 0) {
        double s = 0.0;
#pragma unroll
        for (int j = 0; j < 8; ++j) s += sh[j];
        out[0] = (float)(s * (1.0 / 8192.0));
    }
}

extern "C" void kernel_launch(void* const* d_in, const int* in_sizes, int n_in,
                              void* d_out, int out_size)
{
    const float* x       = (const float*)d_in[0];
    const float* centers = (const float*)d_in[1];
    const int*   labels  = (const int*)d_in[2];
    float*       out     = (float*)d_out;

    loss_main<<<256, 256>>>(x, centers, labels);
    loss_reduce<<<1, 256>>>(out);
}

// round 10
// speedup vs baseline: 1.5971x; 1.5971x over previous
#include <cuda_runtime.h>

// B=8192, D=512, NUM_CLASSES=90, K=8
// Numerics (validated R9): per dot, NEON VF4xIC2 structure:
//   8 independent serial FMA chains, chain j covers elements 8i+j (i=0..63);
//   combine v_e = fadd(chain_e, chain_{e+4}); dot = fadd(fadd(v0,v1),fadd(v2,v3));
//   d = fadd(1,dot). Epilogue f32 per-op rounded, k ascending. Batch mean double.
// This version groups samples by class so center rows are read from SMEM
// (was 128MB of L2 traffic -> now 1.47MB unique + SMEM reuse).

#define NUM_CLASSES 90
#define CHUNKS      16
#define CHUNK_B     512
#define NBLK        (NUM_CLASSES * CHUNKS)   // 1440
#define THREADS     128
#define SLOTS       8
#define CPAD        520                       // padded c row stride (words)

__device__ double g_partials[NBLK];

__global__ __launch_bounds__(THREADS) void loss_main(
    const float* __restrict__ x,
    const float* __restrict__ centers,
    const int* __restrict__ labels)
{
    __shared__ float    cs[8 * CPAD];          // centers, padded rows
    __shared__ float    xsm[SLOTS * 512];      // staged x rows
    __shared__ int      list[CHUNK_B];         // matching sample local indices
    __shared__ unsigned gmask[16];
    __shared__ int      gbase[16];
    __shared__ int      s_n;
    __shared__ float    dk[SLOTS][8];

    const int tid    = threadIdx.x;
    const int cls    = blockIdx.x / CHUNKS;
    const int chunk  = blockIdx.x % CHUNKS;
    const int base_b = chunk * CHUNK_B;
    const int warp   = tid >> 5;
    const int lane   = tid & 31;

    // ---- stage this class's 8 center rows into padded smem (coalesced) ----
    const float4* __restrict__ gc4 =
        reinterpret_cast<const float4*>(centers + (size_t)cls * 8 * 512);
    for (int u = tid; u < 1024; u += THREADS) {
        int row = u >> 7, f4 = u & 127;
        float4 v = gc4[row * 128 + f4];
        *reinterpret_cast<float4*>(&cs[row * CPAD + f4 * 4]) = v;
    }

    // ---- deterministic scan: find samples in this chunk with label==cls ----
#pragma unroll
    for (int q = 0; q < 4; ++q) {
        int g = warp * 4 + q;                       // 16 groups of 32 labels
        int idx = base_b + g * 32 + lane;
        unsigned bal = __ballot_sync(0xFFFFFFFFu, labels[idx] == cls);
        if (lane == 0) gmask[g] = bal;
    }
    __syncthreads();
    if (warp == 0 && lane < 16) {
        int cnt = __popc(gmask[lane]);
        int inc = cnt;
#pragma unroll
        for (int off = 1; off < 16; off <<= 1) {
            int o = __shfl_up_sync(0x0000FFFFu, inc, off);
            if (lane >= off) inc += o;
        }
        gbase[lane] = inc - cnt;
        if (lane == 15) s_n = inc;
    }
    __syncthreads();
#pragma unroll
    for (int q = 0; q < 4; ++q) {
        int g = warp * 4 + q;
        unsigned m = gmask[g];
        if ((m >> lane) & 1u)
            list[gbase[g] + __popc(m & ((1u << lane) - 1u))] = g * 32 + lane;
    }
    __syncthreads();

    const int n  = s_n;
    const int nr = (n + SLOTS - 1) / SLOTS;
    double bsum = 0.0;

    const int s     = tid >> 4;      // slot 0..7
    const int k     = (tid >> 1) & 7;
    const int h     = tid & 1;       // 0 = va chains (elems 8i+0..3), 1 = vb
    const int tslot = tid & 15;

    for (int r = 0; r < nr; ++r) {
        const int si = r * SLOTS + s;
        // stage x row for this slot (16 threads per slot, coalesced float4)
        if (si < n) {
            int b = base_b + list[si];
            const float4* __restrict__ x4 =
                reinterpret_cast<const float4*>(x + (size_t)b * 512);
#pragma unroll
            for (int v = 0; v < 8; ++v) {
                int f4 = tslot + 16 * v;
                *reinterpret_cast<float4*>(&xsm[s * 512 + f4 * 4]) = x4[f4];
            }
        }
        __syncthreads();

        // serial packet chain: acc = va (h=0) or vb (h=1), EXACT R9 order
        float4 acc = make_float4(0.f, 0.f, 0.f, 0.f);
        const float* xb = &xsm[s * 512 + h * 4];
        const float* cb = &cs[k * CPAD + h * 4];
#pragma unroll
        for (int i = 0; i < 64; ++i) {
            float4 xv = *reinterpret_cast<const float4*>(xb + i * 8);
            float4 cv = *reinterpret_cast<const float4*>(cb + i * 8);
            acc.x = fmaf(xv.x, cv.x, acc.x);
            acc.y = fmaf(xv.y, cv.y, acc.y);
            acc.z = fmaf(xv.z, cv.z, acc.z);
            acc.w = fmaf(xv.w, cv.w, acc.w);
        }
        // combine with partner chain (h^1); IEEE add is bitwise-commutative
        float px = __shfl_xor_sync(0xFFFFFFFFu, acc.x, 1);
        float py = __shfl_xor_sync(0xFFFFFFFFu, acc.y, 1);
        float pz = __shfl_xor_sync(0xFFFFFFFFu, acc.z, 1);
        float pw = __shfl_xor_sync(0xFFFFFFFFu, acc.w, 1);
        float v0 = __fadd_rn(acc.x, px);
        float v1 = __fadd_rn(acc.y, py);
        float v2 = __fadd_rn(acc.z, pz);
        float v3 = __fadd_rn(acc.w, pw);
        float dot = __fadd_rn(__fadd_rn(v0, v1), __fadd_rn(v2, v3));
        float d = __fadd_rn(1.0f, dot);
        if (h == 0 && si < n) dk[s][k] = d;
        __syncthreads();

        if (tid == 0) {
            int cnt = n - r * SLOTS;
            if (cnt > SLOTS) cnt = SLOTS;
            for (int ss = 0; ss < cnt; ++ss) {
                float dl[8];
#pragma unroll
                for (int j = 0; j < 8; ++j) dl[j] = dk[ss][j];
                float s1 = dl[0];
#pragma unroll
                for (int j = 1; j < 8; ++j) s1 = __fadd_rn(s1, dl[j]);
                float accw = 0.f;
#pragma unroll
                for (int j = 0; j < 8; ++j) {
                    float w = __fdiv_rn(dl[j], s1);
                    float p = __fmul_rn(w, dl[j]);
                    accw = __fadd_rn(accw, p);
                }
                bsum += (double)accw;
            }
        }
        __syncthreads();
    }
    if (tid == 0) g_partials[blockIdx.x] = bsum;
}

__global__ __launch_bounds__(256) void loss_reduce(float* __restrict__ out)
{
    __shared__ double sh[8];
    const int tid = threadIdx.x;
    const int lane = tid & 31;
    const int w = tid >> 5;

    double v = 0.0;
    for (int i = tid; i < NBLK; i += 256) v += g_partials[i];
#pragma unroll
    for (int m = 16; m >= 1; m >>= 1)
        v += __shfl_xor_sync(0xFFFFFFFFu, v, m);
    if (lane == 0) sh[w] = v;
    __syncthreads();
    if (tid == 0) {
        double t = 0.0;
#pragma unroll
        for (int j = 0; j < 8; ++j) t += sh[j];
        out[0] = (float)(t * (1.0 / 8192.0));
    }
}

extern "C" void kernel_launch(void* const* d_in, const int* in_sizes, int n_in,
                              void* d_out, int out_size)
{
    const float* x       = (const float*)d_in[0];
    const float* centers = (const float*)d_in[1];
    const int*   labels  = (const int*)d_in[2];
    float*       out     = (float*)d_out;

    loss_main<<<NBLK, THREADS>>>(x, centers, labels);
    loss_reduce<<<1, 256>>>(out);
}